// round 10
// baseline (speedup 1.0000x reference)
#include <cuda_runtime.h>

// NSLayer via identity (I - x x^T)^k x = x (I - x^T x)^k:
//   out = x @ T,  T = sum_k g_k Abar^k,  Abar = I - x^T x (symmetric).
// Symmetric triangular Horner vectorized by packing TWO MATRICES per thread
// into f32x2 lanes (thread t of a 64-thread block owns matrices t and t+64).
// The Horner update T <- Abar*T + c I runs IN PLACE column-by-column:
// outputs of column j overwrite exactly the triangle slots (i,j) i<=j that
// become dead after column j, so no second 36-entry buffer is ever live.
// Peak live regs ~ Abar(72) + T(72) + col snapshot(16) -> no spills.

#define NTHR 64
#define MPB  128          // matrices per block (2 per thread)
#define SROW 66           // floats per matrix region (64 + pad); odd u64 stride

typedef unsigned long long u64;

__device__ __forceinline__ u64 pack2(float a, float b) {
    u64 r; asm("mov.b64 %0, {%1, %2};" : "=l"(r) : "f"(a), "f"(b)); return r;
}
__device__ __forceinline__ void unpack2(u64 v, float &a, float &b) {
    asm("mov.b64 {%0, %1}, %2;" : "=f"(a), "=f"(b) : "l"(v));
}
__device__ __forceinline__ u64 fma2(u64 a, u64 b, u64 c) {
    u64 d; asm("fma.rn.f32x2 %0, %1, %2, %3;" : "=l"(d) : "l"(a), "l"(b), "l"(c)); return d;
}
__device__ __forceinline__ u64 mul2(u64 a, u64 b) {
    u64 d; asm("mul.rn.f32x2 %0, %1, %2;" : "=l"(d) : "l"(a), "l"(b)); return d;
}

__device__ __forceinline__ constexpr int tix(int i, int j) {  // i <= j
    return 8 * i - (i * (i - 1)) / 2 + (j - i);
}
__device__ __forceinline__ constexpr int symq(int i, int j) {
    return (i <= j) ? tix(i, j) : tix(j, i);
}

__global__ void __launch_bounds__(NTHR)
ns_kernel(const float* __restrict__ x, const float* __restrict__ w,
          float* __restrict__ out)
{
    __shared__ float s[MPB * SROW];   // 33792 B: input staging only
    const int tid = threadIdx.x;
    const long long base = (long long)blockIdx.x * MPB * 64;

    // ---- stage in: coalesced float4 gmem -> padded smem ----
    const float4* __restrict__ gin = (const float4*)(x + base);
#pragma unroll
    for (int v = 0; v < 32; v++) {
        int g4 = tid + NTHR * v;              // 2048 float4 per block
        float4 d = gin[g4];
        int m = g4 >> 4, e = (g4 & 15) << 2;
        float2* p = (float2*)&s[m * SROW + e];
        p[0] = make_float2(d.x, d.y);
        p[1] = make_float2(d.z, d.w);
    }
    __syncthreads();

    // g7=w6 ... g1=w0, g0=w7+1 (identity + outer "+x" folded in)
    const u64 C7 = pack2(w[6], w[6]);
    const u64 D6 = pack2(w[5], w[5]);
    u64 CS[6];
    CS[0] = pack2(w[4], w[4]);
    CS[1] = pack2(w[3], w[3]);
    CS[2] = pack2(w[2], w[2]);
    CS[3] = pack2(w[1], w[1]);
    CS[4] = pack2(w[0], w[0]);
    CS[5] = pack2(w[7] + 1.0f, w[7] + 1.0f);
    const u64 NEG1 = pack2(-1.0f, -1.0f);
    const u64 ONE2 = pack2(1.0f, 1.0f);

    const float* __restrict__ sA = &s[tid * SROW];           // matrix A
    const float* __restrict__ sB = &s[(tid + NTHR) * SROW];  // matrix B

    // ---- Gram: G = x^T x over rows, lanes = {matA, matB} ----
    u64 Ab[36];
#pragma unroll
    for (int q = 0; q < 36; q++) Ab[q] = 0ULL;

#pragma unroll
    for (int k = 0; k < 8; k++) {
        u64 xk[8];
#pragma unroll
        for (int q = 0; q < 4; q++) {
            u64 va = *(const u64*)&sA[k * 8 + 2 * q];
            u64 vb = *(const u64*)&sB[k * 8 + 2 * q];
            float a0, a1, b0, b1;
            unpack2(va, a0, a1);
            unpack2(vb, b0, b1);
            xk[2 * q]     = pack2(a0, b0);
            xk[2 * q + 1] = pack2(a1, b1);
        }
#pragma unroll
        for (int i = 0; i < 8; i++)
#pragma unroll
            for (int j = i; j < 8; j++)
                Ab[tix(i, j)] = fma2(xk[i], xk[j], Ab[tix(i, j)]);
    }

    // ---- Abar = I - G (in place) ----
#pragma unroll
    for (int i = 0; i < 8; i++)
#pragma unroll
        for (int j = i; j < 8; j++)
            Ab[tix(i, j)] = fma2(Ab[tix(i, j)], NEG1, (i == j) ? ONE2 : 0ULL);

    // ---- T = g7*Abar + g6*I ----
    u64 T[36];
#pragma unroll
    for (int i = 0; i < 8; i++)
#pragma unroll
        for (int j = i; j < 8; j++)
            T[tix(i, j)] = fma2(Ab[tix(i, j)], C7, (i == j) ? D6 : 0ULL);

    // ---- 6 Horner steps, IN PLACE: T <- Abar*T + c I ----
    // Column order j=0..7. Slots (i,j) i<=j die after column j and are
    // overwritten by that column's outputs; later columns never read them.
#pragma unroll
    for (int sIdx = 0; sIdx < 6; sIdx++) {
#pragma unroll
        for (int j = 0; j < 8; j++) {
            u64 colT[8];                       // snapshot of old column j
#pragma unroll
            for (int m = 0; m < 8; m++) colT[m] = T[symq(m, j)];
#pragma unroll
            for (int i = 0; i <= j; i++) {
                u64 a = (i == j) ? CS[sIdx] : 0ULL;
#pragma unroll
                for (int m = 0; m < 8; m++)
                    a = fma2(Ab[symq(i, m)], colT[m], a);
                T[tix(i, j)] = a;
            }
        }
    }

    // ---- out = x @ T, rows straight to gmem (no smem round trip) ----
    float* __restrict__ goutA = out + base + (long long)tid * 64;
    float* __restrict__ goutB = goutA + (long long)NTHR * 64;
#pragma unroll
    for (int i = 0; i < 8; i++) {
        u64 xk[8];
#pragma unroll
        for (int q = 0; q < 4; q++) {
            u64 va = *(const u64*)&sA[i * 8 + 2 * q];
            u64 vb = *(const u64*)&sB[i * 8 + 2 * q];
            float a0, a1, b0, b1;
            unpack2(va, a0, a1);
            unpack2(vb, b0, b1);
            xk[2 * q]     = pack2(a0, b0);
            xk[2 * q + 1] = pack2(a1, b1);
        }
        float oa[8], ob[8];
#pragma unroll
        for (int j = 0; j < 8; j++) {
            u64 a = mul2(xk[0], T[symq(0, j)]);
#pragma unroll
            for (int k = 1; k < 8; k++)
                a = fma2(xk[k], T[symq(k, j)], a);
            unpack2(a, oa[j], ob[j]);
        }
        ((float4*)(goutA + i * 8))[0] = make_float4(oa[0], oa[1], oa[2], oa[3]);
        ((float4*)(goutA + i * 8))[1] = make_float4(oa[4], oa[5], oa[6], oa[7]);
        ((float4*)(goutB + i * 8))[0] = make_float4(ob[0], ob[1], ob[2], ob[3]);
        ((float4*)(goutB + i * 8))[1] = make_float4(ob[4], ob[5], ob[6], ob[7]);
    }
}

extern "C" void kernel_launch(void* const* d_in, const int* in_sizes, int n_in,
                              void* d_out, int out_size) {
    const float* x = (const float*)d_in[0];   // (2048,128,8,8) fp32
    const float* w = (const float*)d_in[1];   // (14,) fp32
    float* out = (float*)d_out;

    int nmat = in_sizes[0] / 64;              // 262144
    int grid = nmat / MPB;                    // 2048
    ns_kernel<<<grid, NTHR>>>(x, w, out);
}